// round 10
// baseline (speedup 1.0000x reference)
#include <cuda_runtime.h>
#include <cstdint>

// Per-token int4 quantization — 128-thread CTA, one row, 8-deep load batch:
//   x: [N, H] fp32 (H = 4096)
//   scales[n] = max|x[n,:]| / 7
//   q = rint(x * 7/max)   (in [-7,7] by construction; clamp-free)
//   packed byte = ((q_odd & 0xF) << 4) | (q_even & 0xF)  (signed int8 value)
//
// 128 threads/CTA: barrier couples only 4 warps (shorter load-tail gate),
// 8 front-batched LDG.128 per thread (MLP_p1=8), 2x CTAs per SM vs 256-thr
// version for finer load/store phase interleaving across CTAs.
//
// Cache policy: loads __ldcs (streaming input, read once); stores default
// write-back (graph replays overwrite d_out; L2-resident dirty lines never
// cost DRAM write bandwidth — measured -47MB DRAM traffic in R8).
//
// Harness output layout (detected via out_size):
//   FLOAT_OUT: [N*H/2 float32 (packed byte values)][N float32 scales]
//   BYTE_OUT : [N*H/2 int8][N float32 scales]

constexpr int H       = 4096;
constexpr int THREADS = 128;
constexpr int CHUNKS  = H / 4 / THREADS;  // 8 float4-chunks per thread

template <bool FLOAT_OUT>
__global__ __launch_bounds__(THREADS, 16)
void quant_int4_kernel(const float* __restrict__ x,
                       void* __restrict__ packed_out,
                       float* __restrict__ scales)
{
    const int row = blockIdx.x;
    const int t   = threadIdx.x;

    const float4* xr = reinterpret_cast<const float4*>(x + (size_t)row * H);

    // 8 front-batched lane-consecutive streaming loads.
    float4 v[CHUNKS];
#pragma unroll
    for (int k = 0; k < CHUNKS; ++k)
        v[k] = __ldcs(&xr[t + THREADS * k]);

    // Local max|x|
    float m = 0.0f;
#pragma unroll
    for (int k = 0; k < CHUNKS; ++k) {
        m = fmaxf(m, fmaxf(fmaxf(fabsf(v[k].x), fabsf(v[k].y)),
                           fmaxf(fabsf(v[k].z), fabsf(v[k].w))));
    }

    // Warp reduce
#pragma unroll
    for (int o = 16; o > 0; o >>= 1)
        m = fmaxf(m, __shfl_xor_sync(0xffffffffu, m, o));

    __shared__ float smax[THREADS / 32];
    if ((t & 31) == 0) smax[t >> 5] = m;
    __syncthreads();   // couples only 4 warps

    float rowmax = smax[0];
#pragma unroll
    for (int w = 1; w < THREADS / 32; ++w)
        rowmax = fmaxf(rowmax, smax[w]);

    const float scale = rowmax / 7.0f;                        // exact fp32
    const float inv   = (rowmax > 0.0f) ? 7.0f / rowmax : 0.0f;

    if (t == 0) scales[row] = scale;

    if (FLOAT_OUT) {
        float2* op = reinterpret_cast<float2*>((float*)packed_out + (size_t)row * (H / 2));
#pragma unroll
        for (int k = 0; k < CHUNKS; ++k) {
            // rintf == FRND round-half-even, matches reference rounding.
            float q0 = rintf(v[k].x * inv);
            float q1 = rintf(v[k].y * inv);
            float q2 = rintf(v[k].z * inv);
            float q3 = rintf(v[k].w * inv);
            // low-nibble value: q + 16 if q < 0 (maps [-8,-1] -> [8,15])
            float n0 = q0 + (q0 < 0.0f ? 16.0f : 0.0f);
            float n2 = q2 + (q2 < 0.0f ? 16.0f : 0.0f);
            op[t + THREADS * k] = make_float2(fmaf(16.0f, q1, n0),
                                              fmaf(16.0f, q3, n2));
        }
    } else {
        uint16_t* op = reinterpret_cast<uint16_t*>((int8_t*)packed_out + (size_t)row * (H / 2));
#pragma unroll
        for (int k = 0; k < CHUNKS; ++k) {
            int q0 = __float2int_rn(v[k].x * inv);
            int q1 = __float2int_rn(v[k].y * inv);
            int q2 = __float2int_rn(v[k].z * inv);
            int q3 = __float2int_rn(v[k].w * inv);
            op[t + THREADS * k] = (uint16_t)((((q3 & 0xF) << 4) | (q2 & 0xF)) << 8
                                           | (((q1 & 0xF) << 4) | (q0 & 0xF)));
        }
    }
}

extern "C" void kernel_launch(void* const* d_in, const int* in_sizes, int n_in,
                              void* d_out, int out_size)
{
    const float* x = (const float*)d_in[0];
    const int rows = in_sizes[0] / H;
    const long long packed_elems = (long long)rows * (H / 2);

    if ((long long)out_size == packed_elems + rows) {
        // float32 layout: packed values as floats, then scales
        float* packed = (float*)d_out;
        float* scales = packed + packed_elems;
        quant_int4_kernel<true><<<rows, THREADS>>>(x, packed, scales);
    } else {
        // int8 layout: packed bytes, then fp32 scales appended as raw bytes
        int8_t* packed = (int8_t*)d_out;
        float*  scales = (float*)(packed + packed_elems);
        quant_int4_kernel<false><<<rows, THREADS>>>(x, packed, scales);
    }
}

// round 11
// speedup vs baseline: 1.1735x; 1.1735x over previous
#include <cuda_runtime.h>
#include <cstdint>

// Per-token int4 quantization — two rows per CTA, SEQUENCED schedule:
//   loads A -> loads B (both in flight) -> reduce A (barrier 1) ->
//   store A (B loads drain underneath) -> reduce B (barrier 2) -> store B.
// Row-A stores gate only on row-A loads, unlike the fused-barrier variant.
//
//   x: [N, H] fp32 (H = 4096)
//   scales[n] = max|x[n,:]| / 7
//   q = rint(x * 7/max)   (in [-7,7] by construction; clamp-free)
//   packed byte = ((q_odd & 0xF) << 4) | (q_even & 0xF)  (signed int8 value)
//
// Cache policy: loads __ldcs (streaming input); stores default write-back
// (graph replays overwrite d_out; L2-resident dirty lines skip DRAM).
//
// Harness output layout (detected via out_size):
//   FLOAT_OUT: [N*H/2 float32 (packed byte values)][N float32 scales]
//   BYTE_OUT : [N*H/2 int8][N float32 scales]

constexpr int H       = 4096;
constexpr int THREADS = 256;
constexpr int CHUNKS  = H / 4 / THREADS;  // 4 float4-chunks per thread per row

template <bool FLOAT_OUT>
__device__ __forceinline__ void emit_row(const float4* __restrict__ v,
                                         float inv, void* __restrict__ rowp, int t)
{
    if (FLOAT_OUT) {
        float2* op = reinterpret_cast<float2*>(rowp);
#pragma unroll
        for (int k = 0; k < CHUNKS; ++k) {
            float q0 = rintf(v[k].x * inv);
            float q1 = rintf(v[k].y * inv);
            float q2 = rintf(v[k].z * inv);
            float q3 = rintf(v[k].w * inv);
            float n0 = q0 + (q0 < 0.0f ? 16.0f : 0.0f);
            float n2 = q2 + (q2 < 0.0f ? 16.0f : 0.0f);
            op[t + THREADS * k] = make_float2(fmaf(16.0f, q1, n0),
                                              fmaf(16.0f, q3, n2));
        }
    } else {
        uint16_t* op = reinterpret_cast<uint16_t*>(rowp);
#pragma unroll
        for (int k = 0; k < CHUNKS; ++k) {
            int q0 = __float2int_rn(v[k].x * inv);
            int q1 = __float2int_rn(v[k].y * inv);
            int q2 = __float2int_rn(v[k].z * inv);
            int q3 = __float2int_rn(v[k].w * inv);
            op[t + THREADS * k] = (uint16_t)((((q3 & 0xF) << 4) | (q2 & 0xF)) << 8
                                           | (((q1 & 0xF) << 4) | (q0 & 0xF)));
        }
    }
}

__device__ __forceinline__ float warp_max_abs(const float4* __restrict__ v)
{
    float m = 0.0f;
#pragma unroll
    for (int k = 0; k < CHUNKS; ++k)
        m = fmaxf(m, fmaxf(fmaxf(fabsf(v[k].x), fabsf(v[k].y)),
                           fmaxf(fabsf(v[k].z), fabsf(v[k].w))));
#pragma unroll
    for (int o = 16; o > 0; o >>= 1)
        m = fmaxf(m, __shfl_xor_sync(0xffffffffu, m, o));
    return m;
}

template <bool FLOAT_OUT>
__global__ __launch_bounds__(THREADS, 4)
void quant_int4_kernel(const float* __restrict__ x,
                       void* __restrict__ packed_out,
                       float* __restrict__ scales)
{
    const int rowA = 2 * blockIdx.x;
    const int rowB = rowA + 1;
    const int t    = threadIdx.x;

    const float4* xa = reinterpret_cast<const float4*>(x + (size_t)rowA * H);
    const float4* xb = reinterpret_cast<const float4*>(x + (size_t)rowB * H);

    __shared__ float smaxA[THREADS / 32];
    __shared__ float smaxB[THREADS / 32];

    // Issue all 8 loads (A then B) — both rows in flight.
    float4 va[CHUNKS], vb[CHUNKS];
#pragma unroll
    for (int k = 0; k < CHUNKS; ++k) va[k] = __ldcs(&xa[t + THREADS * k]);
#pragma unroll
    for (int k = 0; k < CHUNKS; ++k) vb[k] = __ldcs(&xb[t + THREADS * k]);

    // ── Row A: reduce + barrier (gates only on va) ──
    float ma = warp_max_abs(va);
    if ((t & 31) == 0) smaxA[t >> 5] = ma;
    __syncthreads();

    float rmaxA = smaxA[0];
#pragma unroll
    for (int w = 1; w < THREADS / 32; ++w) rmaxA = fmaxf(rmaxA, smaxA[w]);
    const float invA = (rmaxA > 0.0f) ? 7.0f / rmaxA : 0.0f;
    if (t == 0) scales[rowA] = rmaxA / 7.0f;

    // Store A while vb loads drain underneath.
    if (FLOAT_OUT)
        emit_row<true >(va, invA, (float*)packed_out + (size_t)rowA * (H / 2), t);
    else
        emit_row<false>(va, invA, (int8_t*)packed_out + (size_t)rowA * (H / 2), t);

    // ── Row B: reduce + barrier + store ──
    float mb = warp_max_abs(vb);
    if ((t & 31) == 0) smaxB[t >> 5] = mb;
    __syncthreads();

    float rmaxB = smaxB[0];
#pragma unroll
    for (int w = 1; w < THREADS / 32; ++w) rmaxB = fmaxf(rmaxB, smaxB[w]);
    const float invB = (rmaxB > 0.0f) ? 7.0f / rmaxB : 0.0f;
    if (t == 0) scales[rowB] = rmaxB / 7.0f;

    if (FLOAT_OUT)
        emit_row<true >(vb, invB, (float*)packed_out + (size_t)rowB * (H / 2), t);
    else
        emit_row<false>(vb, invB, (int8_t*)packed_out + (size_t)rowB * (H / 2), t);
}

extern "C" void kernel_launch(void* const* d_in, const int* in_sizes, int n_in,
                              void* d_out, int out_size)
{
    const float* x = (const float*)d_in[0];
    const int rows = in_sizes[0] / H;   // 8192 (even)
    const long long packed_elems = (long long)rows * (H / 2);

    if ((long long)out_size == packed_elems + rows) {
        float* packed = (float*)d_out;
        float* scales = packed + packed_elems;
        quant_int4_kernel<true><<<rows / 2, THREADS>>>(x, packed, scales);
    } else {
        int8_t* packed = (int8_t*)d_out;
        float*  scales = (float*)(packed + packed_elems);
        quant_int4_kernel<false><<<rows / 2, THREADS>>>(x, packed, scales);
    }
}

// round 13
// speedup vs baseline: 1.2079x; 1.0293x over previous
#include <cuda_runtime.h>
#include <cstdint>

// Per-token int4 quantization (single-pass, block-per-row) — FINAL (R8 config):
//   x: [N, H] fp32 (H = 4096)
//   scales[n] = max|x[n,:]| / 7
//   q = rint(x * 7/max)   (in [-7,7] by construction; clamp-free)
//   packed byte = ((q_odd & 0xF) << 4) | (q_even & 0xF)  (signed int8 value)
//
// Cache policy (measured best, R8):
//   loads : __ldcs (streaming, evict-first — input read exactly once)
//   stores: default write-back — harness replays into the same d_out, so
//           L2-resident dirty output lines are overwritten before writeback;
//           measured DRAM traffic 145MB vs 134MB mandatory reads (writes ~free).
//
// Convergence note: all schedule variants (2-row fused/sequenced, persistent,
// warp-per-row, 128-thr) measured 25.4-34.6us kernel; this config holds the
// best end-to-end dur (31.456us) at the read-dominated HBM roofline.
//
// Harness output layout (detected via out_size):
//   FLOAT_OUT: [N*H/2 float32 (packed byte values)][N float32 scales]
//   BYTE_OUT : [N*H/2 int8][N float32 scales]

constexpr int H       = 4096;
constexpr int THREADS = 256;
constexpr int CHUNKS  = H / 4 / THREADS;  // 4 float4-chunks per thread

template <bool FLOAT_OUT>
__global__ __launch_bounds__(THREADS, 8)
void quant_int4_kernel(const float* __restrict__ x,
                       void* __restrict__ packed_out,
                       float* __restrict__ scales)
{
    const int row = blockIdx.x;
    const int t   = threadIdx.x;

    const float4* xr = reinterpret_cast<const float4*>(x + (size_t)row * H);

    // Coalesced streaming loads: lane-consecutive float4 per LDG.128,
    // all 4 front-batched for max MLP.
    float4 v[CHUNKS];
#pragma unroll
    for (int k = 0; k < CHUNKS; ++k)
        v[k] = __ldcs(&xr[t + THREADS * k]);

    // Local max|x|
    float m = 0.0f;
#pragma unroll
    for (int k = 0; k < CHUNKS; ++k) {
        m = fmaxf(m, fmaxf(fmaxf(fabsf(v[k].x), fabsf(v[k].y)),
                           fmaxf(fabsf(v[k].z), fabsf(v[k].w))));
    }

    // Warp reduce
#pragma unroll
    for (int o = 16; o > 0; o >>= 1)
        m = fmaxf(m, __shfl_xor_sync(0xffffffffu, m, o));

    __shared__ float smax[THREADS / 32];
    if ((t & 31) == 0) smax[t >> 5] = m;
    __syncthreads();

    float rowmax = smax[0];
#pragma unroll
    for (int w = 1; w < THREADS / 32; ++w)
        rowmax = fmaxf(rowmax, smax[w]);

    const float scale = rowmax / 7.0f;                        // exact fp32
    const float inv   = (rowmax > 0.0f) ? 7.0f / rowmax : 0.0f;

    if (t == 0) scales[row] = scale;

    // Quantize each float4 chunk -> 2 packed byte values. Clamp-free:
    // |x| <= rowmax implies |x*inv| <= 7 (+1ulp), rint stays in [-7,7].
    if (FLOAT_OUT) {
        float2* op = reinterpret_cast<float2*>((float*)packed_out + (size_t)row * (H / 2));
#pragma unroll
        for (int k = 0; k < CHUNKS; ++k) {
            // rintf == FRND round-half-even, matches reference rounding.
            float q0 = rintf(v[k].x * inv);
            float q1 = rintf(v[k].y * inv);
            float q2 = rintf(v[k].z * inv);
            float q3 = rintf(v[k].w * inv);
            // low-nibble value: q + 16 if q < 0 (maps [-8,-1] -> [8,15])
            float n0 = q0 + (q0 < 0.0f ? 16.0f : 0.0f);
            float n2 = q2 + (q2 < 0.0f ? 16.0f : 0.0f);
            float b0 = fmaf(16.0f, q1, n0);   // exact: small integers
            float b1 = fmaf(16.0f, q3, n2);
            op[t + THREADS * k] = make_float2(b0, b1);   // default write-back
        }
    } else {
        uint16_t* op = reinterpret_cast<uint16_t*>((int8_t*)packed_out + (size_t)row * (H / 2));
#pragma unroll
        for (int k = 0; k < CHUNKS; ++k) {
            int q0 = __float2int_rn(v[k].x * inv);
            int q1 = __float2int_rn(v[k].y * inv);
            int q2 = __float2int_rn(v[k].z * inv);
            int q3 = __float2int_rn(v[k].w * inv);
            uint16_t b = (uint16_t)((((q3 & 0xF) << 4) | (q2 & 0xF)) << 8
                                  | (((q1 & 0xF) << 4) | (q0 & 0xF)));
            op[t + THREADS * k] = b;
        }
    }
}

extern "C" void kernel_launch(void* const* d_in, const int* in_sizes, int n_in,
                              void* d_out, int out_size)
{
    const float* x = (const float*)d_in[0];
    const int rows = in_sizes[0] / H;
    const long long packed_elems = (long long)rows * (H / 2);

    if ((long long)out_size == packed_elems + rows) {
        // float32 layout: packed values as floats, then scales
        float* packed = (float*)d_out;
        float* scales = packed + packed_elems;
        quant_int4_kernel<true><<<rows, THREADS>>>(x, packed, scales);
    } else {
        // int8 layout: packed bytes, then fp32 scales appended as raw bytes
        int8_t* packed = (int8_t*)d_out;
        float*  scales = (float*)(packed + packed_elems);
        quant_int4_kernel<false><<<rows, THREADS>>>(x, packed, scales);
    }
}